// round 1
// baseline (speedup 1.0000x reference)
#include <cuda_runtime.h>
#include <cstddef>

// ---------------------------------------------------------------------------
// TRecTransformer: linear-attention encoder/decoder, fp32 baseline.
// D_MODEL=512, N_HEADS=8, D_HEAD=64, N_LAYERS=4, D_FF=2048, B=4, L=4096.
// ---------------------------------------------------------------------------

#define NTOK   16384          // B * L
#define DMODEL 512
#define DFF    2048
#define NHEAD  8
#define DHEAD  64
#define LSEQ   4096
#define BATCH  4
#define SCH    16             // s-chunks for kv partial reduction

// ---- scratch layout (floats) ----
#define SZ      ((size_t)NTOK * DMODEL)          // 8,388,608
#define OFF_H    (0*SZ)
#define OFF_Z    (1*SZ)
#define OFF_O    (2*SZ)
#define OFF_Q    (3*SZ)
#define OFF_K    (4*SZ)
#define OFF_V    (5*SZ)
#define OFF_ATTN (6*SZ)
#define OFF_TMP  (7*SZ)
#define OFF_FF   (8*SZ)                          // NTOK*DFF = 4*SZ
#define OFF_PKV  (12*SZ)                         // SCH*32*4096
#define OFF_PKS  (OFF_PKV + (size_t)SCH*32*4096) // SCH*32*64
#define OFF_KV   (OFF_PKS + (size_t)SCH*32*64)   // 32*4096
#define OFF_KS   (OFF_KV  + (size_t)32*4096)     // 32*64
#define TOTAL_F  (OFF_KS + 2048)

__device__ float g_scratch[TOTAL_F];

// ---------------------------------------------------------------------------
// GEMM: C[M,N] = A[M,K] @ W[K,N] + bias[N], optional activation.
// 128x128 tile, BK=8, 256 threads, 8x8 per thread. M,N %128==0, K %8==0.
// ACT: 0 = none, 1 = relu, 2 = phi(x) = x>0 ? x+1 : exp(x)  (elu(x)+1)
// ---------------------------------------------------------------------------
template<int ACT>
__global__ __launch_bounds__(256) void gemm_bias(
    const float* __restrict__ A, const float* __restrict__ W,
    const float* __restrict__ bias, float* __restrict__ C,
    int M, int N, int K)
{
    __shared__ float As[8][128];
    __shared__ float Bs[8][128];
    const int tid  = threadIdx.x;
    const int row0 = blockIdx.y * 128;
    const int col0 = blockIdx.x * 128;
    const int a_row = tid >> 1,  a_col = (tid & 1) << 2;
    const int b_row = tid >> 5,  b_col = (tid & 31) << 2;
    const int tx = tid & 15,     ty = tid >> 4;

    float acc[8][8];
    #pragma unroll
    for (int i = 0; i < 8; i++)
        #pragma unroll
        for (int j = 0; j < 8; j++) acc[i][j] = 0.f;

    const float* Aptr = A + (size_t)(row0 + a_row) * K + a_col;
    const float* Wptr = W + (size_t)b_row * N + col0 + b_col;

    for (int k0 = 0; k0 < K; k0 += 8) {
        float4 av = *reinterpret_cast<const float4*>(Aptr + k0);
        float4 bv = *reinterpret_cast<const float4*>(Wptr + (size_t)k0 * N);
        As[a_col + 0][a_row] = av.x;
        As[a_col + 1][a_row] = av.y;
        As[a_col + 2][a_row] = av.z;
        As[a_col + 3][a_row] = av.w;
        *reinterpret_cast<float4*>(&Bs[b_row][b_col]) = bv;
        __syncthreads();
        #pragma unroll
        for (int k = 0; k < 8; k++) {
            float ar[8], br[8];
            *reinterpret_cast<float4*>(ar)     = *reinterpret_cast<const float4*>(&As[k][ty * 8]);
            *reinterpret_cast<float4*>(ar + 4) = *reinterpret_cast<const float4*>(&As[k][ty * 8 + 4]);
            *reinterpret_cast<float4*>(br)     = *reinterpret_cast<const float4*>(&Bs[k][tx * 8]);
            *reinterpret_cast<float4*>(br + 4) = *reinterpret_cast<const float4*>(&Bs[k][tx * 8 + 4]);
            #pragma unroll
            for (int i = 0; i < 8; i++)
                #pragma unroll
                for (int j = 0; j < 8; j++)
                    acc[i][j] = fmaf(ar[i], br[j], acc[i][j]);
        }
        __syncthreads();
    }

    #pragma unroll
    for (int i = 0; i < 8; i++) {
        const size_t r = (size_t)(row0 + ty * 8 + i);
        #pragma unroll
        for (int j = 0; j < 8; j++) {
            const int c = col0 + tx * 8 + j;
            float v = acc[i][j] + bias[c];
            if (ACT == 1) v = fmaxf(v, 0.f);
            if (ACT == 2) v = v > 0.f ? v + 1.f : __expf(v);
            C[r * N + c] = v;
        }
    }
}

// ---------------------------------------------------------------------------
// kv partial: pkv[ch,bh,d,m] = sum_{s in chunk} K[b,s,h,d] * V[b,s,h,m]
//             pks[ch,bh,d]   = sum K
// grid (32, SCH), 256 threads. K,V are [B*L, 512] post-projection (phi on K).
// ---------------------------------------------------------------------------
__global__ __launch_bounds__(256) void kv_partial(
    const float* __restrict__ Kt, const float* __restrict__ Vt,
    float* __restrict__ pkv, float* __restrict__ pks)
{
    const int bh = blockIdx.x, ch = blockIdx.y;
    const int b = bh >> 3, h = bh & 7;
    const int tid = threadIdx.x;
    __shared__ float Ks[4][64], Vs[4][64];

    float acc[16];
    #pragma unroll
    for (int j = 0; j < 16; j++) acc[j] = 0.f;
    float ksa = 0.f;

    const int   s0   = ch * (LSEQ / SCH);
    const size_t base = ((size_t)b * LSEQ) * DMODEL + h * DHEAD;
    const int r = tid >> 6, d = tid & 63;

    for (int s = s0; s < s0 + LSEQ / SCH; s += 4) {
        const size_t off = base + (size_t)(s + r) * DMODEL + d;
        Ks[r][d] = Kt[off];
        Vs[r][d] = Vt[off];
        __syncthreads();
        #pragma unroll
        for (int rr = 0; rr < 4; rr++) {
            #pragma unroll
            for (int j = 0; j < 16; j++) {
                const int flat = j * 256 + tid;
                acc[j] = fmaf(Ks[rr][flat >> 6], Vs[rr][flat & 63], acc[j]);
            }
            if (tid < 64) ksa += Ks[rr][tid];
        }
        __syncthreads();
    }

    float* o = pkv + ((size_t)ch * 32 + bh) * 4096;
    #pragma unroll
    for (int j = 0; j < 16; j++) o[j * 256 + tid] = acc[j];
    if (tid < 64) pks[((size_t)ch * 32 + bh) * 64 + tid] = ksa;
}

__global__ __launch_bounds__(256) void kv_reduce(
    const float* __restrict__ pkv, const float* __restrict__ pks,
    float* __restrict__ kv, float* __restrict__ ks)
{
    const int bh = blockIdx.x, tid = threadIdx.x;
    for (int e = tid; e < 4096; e += 256) {
        float s = 0.f;
        #pragma unroll
        for (int c = 0; c < SCH; c++) s += pkv[((size_t)c * 32 + bh) * 4096 + e];
        kv[(size_t)bh * 4096 + e] = s;
    }
    if (tid < 64) {
        float s = 0.f;
        #pragma unroll
        for (int c = 0; c < SCH; c++) s += pks[((size_t)c * 32 + bh) * 64 + tid];
        ks[bh * 64 + tid] = s;
    }
}

// ---------------------------------------------------------------------------
// attn out: O[b,l,h,m] = (sum_d Q_d * kv[d,m]) / (Q . ksum + eps)
// grid (32, 32), 256 threads (8 warps, 1 token per warp per iter).
// ---------------------------------------------------------------------------
__global__ __launch_bounds__(256) void attn_out(
    const float* __restrict__ Q, const float* __restrict__ kv,
    const float* __restrict__ ksum, float* __restrict__ O)
{
    const int bh = blockIdx.x, b = bh >> 3, h = bh & 7;
    __shared__ float kvs[64][64];
    __shared__ float kss[64];
    const int tid = threadIdx.x;
    for (int e = tid; e < 4096; e += 256) kvs[e >> 6][e & 63] = kv[(size_t)bh * 4096 + e];
    if (tid < 64) kss[tid] = ksum[bh * 64 + tid];
    __syncthreads();

    const int warp = tid >> 5, lane = tid & 31;
    const int tpb = LSEQ / gridDim.y;     // 128
    const int l0 = blockIdx.y * tpb;

    for (int l = l0 + warp; l < l0 + tpb; l += 8) {
        const float* q = Q + ((size_t)(b * LSEQ + l)) * DMODEL + h * DHEAD;
        const float q0 = q[lane], q1 = q[lane + 32];
        float zd = q0 * kss[lane] + q1 * kss[lane + 32];
        #pragma unroll
        for (int o = 16; o > 0; o >>= 1) zd += __shfl_xor_sync(0xffffffffu, zd, o);
        const float z = 1.f / (zd + 1e-6f);

        float a0 = 0.f, a1 = 0.f;
        #pragma unroll
        for (int dd = 0; dd < 32; dd++) {
            const float qd = __shfl_sync(0xffffffffu, q0, dd);
            a0 = fmaf(qd, kvs[dd][lane],      a0);
            a1 = fmaf(qd, kvs[dd][lane + 32], a1);
        }
        #pragma unroll
        for (int dd = 0; dd < 32; dd++) {
            const float qd = __shfl_sync(0xffffffffu, q1, dd);
            a0 = fmaf(qd, kvs[dd + 32][lane],      a0);
            a1 = fmaf(qd, kvs[dd + 32][lane + 32], a1);
        }
        float* op = O + ((size_t)(b * LSEQ + l)) * DMODEL + h * DHEAD;
        op[lane]      = a0 * z;
        op[lane + 32] = a1 * z;
    }
}

// ---------------------------------------------------------------------------
// LayerNorm: Y[t] = LN(X[t] + R[t]) * gamma + beta. One block per token.
// gb: [2,512] = gamma then beta. R may be nullptr.
// ---------------------------------------------------------------------------
__global__ __launch_bounds__(128) void ln_kernel(
    const float* __restrict__ X, const float* __restrict__ R,
    const float* __restrict__ gb, float* __restrict__ Y)
{
    const int t = blockIdx.x, tid = threadIdx.x;
    const float* x = X + (size_t)t * DMODEL;
    float v[4];
    float s = 0.f;
    #pragma unroll
    for (int i = 0; i < 4; i++) {
        float val = x[tid + i * 128];
        if (R) val += R[(size_t)t * DMODEL + tid + i * 128];
        v[i] = val; s += val;
    }
    __shared__ float red[4];
    #pragma unroll
    for (int o = 16; o > 0; o >>= 1) s += __shfl_xor_sync(0xffffffffu, s, o);
    if ((tid & 31) == 0) red[tid >> 5] = s;
    __syncthreads();
    const float mu = (red[0] + red[1] + red[2] + red[3]) * (1.f / DMODEL);
    float qq = 0.f;
    #pragma unroll
    for (int i = 0; i < 4; i++) { const float dd = v[i] - mu; qq += dd * dd; }
    #pragma unroll
    for (int o = 16; o > 0; o >>= 1) qq += __shfl_xor_sync(0xffffffffu, qq, o);
    __syncthreads();
    if ((tid & 31) == 0) red[tid >> 5] = qq;
    __syncthreads();
    const float var = (red[0] + red[1] + red[2] + red[3]) * (1.f / DMODEL);
    const float rstd = rsqrtf(var + 1e-5f);
    #pragma unroll
    for (int i = 0; i < 4; i++) {
        const int j = tid + i * 128;
        Y[(size_t)t * DMODEL + j] = (v[i] - mu) * rstd * gb[j] + gb[DMODEL + j];
    }
}

// ---------------------------------------------------------------------------
// Embedding: h[:,0:256] = x @ emb_w + emb_b ; h[:,256:512] = pe_input[l]
// ---------------------------------------------------------------------------
__global__ void embed_kernel(
    const float* __restrict__ x, const float* __restrict__ pe,
    const float* __restrict__ ew, const float* __restrict__ eb,
    float* __restrict__ h)
{
    const size_t idx = (size_t)blockIdx.x * blockDim.x + threadIdx.x;
    const int tok = (int)(idx >> 9);
    const int j   = (int)(idx & 511);
    const int l   = tok & (LSEQ - 1);
    float val;
    if (j < 256) val = x[(size_t)tok * 2] * ew[j] + x[(size_t)tok * 2 + 1] * ew[256 + j] + eb[j];
    else         val = pe[(size_t)l * 256 + (j - 256)];
    h[idx] = val;
}

__global__ void dec_init_kernel(const float* __restrict__ ope, float* __restrict__ o)
{
    const size_t idx = (size_t)blockIdx.x * blockDim.x + threadIdx.x;
    const size_t tok = idx >> 9;
    o[idx] = ope[((tok & (LSEQ - 1)) << 9) | (idx & 511)];
}

// ---------------------------------------------------------------------------
// Final prediction head: out[t,c] = X[t,:] . pred_w[:,c] + pred_b[c]
// one warp per token.
// ---------------------------------------------------------------------------
__global__ void pred_kernel(
    const float* __restrict__ Xf, const float* __restrict__ pw,
    const float* __restrict__ pb, float* __restrict__ out)
{
    const int gw = (int)(((size_t)blockIdx.x * blockDim.x + threadIdx.x) >> 5);
    const int lane = threadIdx.x & 31;
    if (gw >= NTOK) return;
    const float* xr = Xf + (size_t)gw * DMODEL;
    float a0 = 0.f, a1 = 0.f;
    #pragma unroll 4
    for (int j = lane; j < DMODEL; j += 32) {
        const float v = xr[j];
        a0 = fmaf(v, pw[2 * j],     a0);
        a1 = fmaf(v, pw[2 * j + 1], a1);
    }
    #pragma unroll
    for (int o = 16; o > 0; o >>= 1) {
        a0 += __shfl_xor_sync(0xffffffffu, a0, o);
        a1 += __shfl_xor_sync(0xffffffffu, a1, o);
    }
    if (lane == 0) { out[2 * gw] = a0 + pb[0]; out[2 * gw + 1] = a1 + pb[1]; }
}

// ---------------------------------------------------------------------------
// Host orchestration
// ---------------------------------------------------------------------------
static inline void gemm(int act, const float* A, const float* W, const float* b,
                        float* C, int M, int N, int K)
{
    dim3 grid(N / 128, M / 128);
    if (act == 0)      gemm_bias<0><<<grid, 256>>>(A, W, b, C, M, N, K);
    else if (act == 1) gemm_bias<1><<<grid, 256>>>(A, W, b, C, M, N, K);
    else               gemm_bias<2><<<grid, 256>>>(A, W, b, C, M, N, K);
}

// w: [4][512][512], b: [4][512]; result (post out-projection) in S+OFF_TMP.
static void attention_block(const float* xq, const float* xkv,
                            const float* w, const float* b, float* S)
{
    float* q    = S + OFF_Q;
    float* k    = S + OFF_K;
    float* v    = S + OFF_V;
    float* attn = S + OFF_ATTN;
    float* tmp  = S + OFF_TMP;
    const size_t WS = (size_t)DMODEL * DMODEL;   // 262144

    gemm(2, xq,  w + 0 * WS, b + 0 * DMODEL, q, NTOK, DMODEL, DMODEL);  // Q = phi(xq Wq + bq)
    gemm(2, xkv, w + 1 * WS, b + 1 * DMODEL, k, NTOK, DMODEL, DMODEL);  // K = phi(...)
    gemm(0, xkv, w + 2 * WS, b + 2 * DMODEL, v, NTOK, DMODEL, DMODEL);  // V

    kv_partial<<<dim3(32, SCH), 256>>>(k, v, S + OFF_PKV, S + OFF_PKS);
    kv_reduce<<<32, 256>>>(S + OFF_PKV, S + OFF_PKS, S + OFF_KV, S + OFF_KS);
    attn_out<<<dim3(32, 32), 256>>>(q, S + OFF_KV, S + OFF_KS, attn);

    gemm(0, attn, w + 3 * WS, b + 3 * DMODEL, tmp, NTOK, DMODEL, DMODEL);
}

extern "C" void kernel_launch(void* const* d_in, const int* in_sizes, int n_in,
                              void* d_out, int out_size)
{
    const float* x            = (const float*)d_in[0];
    const float* out_pos_emb  = (const float*)d_in[1];
    const float* pe_input     = (const float*)d_in[2];
    const float* emb_w        = (const float*)d_in[3];
    const float* emb_b        = (const float*)d_in[4];
    const float* enc_attn_w   = (const float*)d_in[5];
    const float* enc_attn_b   = (const float*)d_in[6];
    const float* enc_ln       = (const float*)d_in[7];
    const float* enc_ff_w1    = (const float*)d_in[8];
    const float* enc_ff_b1    = (const float*)d_in[9];
    const float* enc_ff_w2    = (const float*)d_in[10];
    const float* enc_ff_b2    = (const float*)d_in[11];
    const float* enc_final_ln = (const float*)d_in[12];
    const float* dec_self_w   = (const float*)d_in[13];
    const float* dec_self_b   = (const float*)d_in[14];
    const float* dec_cross_w  = (const float*)d_in[15];
    const float* dec_cross_b  = (const float*)d_in[16];
    const float* dec_ln       = (const float*)d_in[17];
    const float* dec_ff_w1    = (const float*)d_in[18];
    const float* dec_ff_b1    = (const float*)d_in[19];
    const float* dec_ff_w2    = (const float*)d_in[20];
    const float* dec_ff_b2    = (const float*)d_in[21];
    const float* dec_final_ln = (const float*)d_in[22];
    const float* pred_w       = (const float*)d_in[23];
    const float* pred_b       = (const float*)d_in[24];

    float* S = nullptr;
    cudaGetSymbolAddress((void**)&S, g_scratch);

    float* h   = S + OFF_H;
    float* z   = S + OFF_Z;
    float* o   = S + OFF_O;
    float* tmp = S + OFF_TMP;
    float* ff  = S + OFF_FF;

    const size_t WS4 = (size_t)4 * DMODEL * DMODEL;  // per-layer attn weight block
    const size_t W1S = (size_t)DMODEL * DFF;
    const size_t W2S = (size_t)DFF * DMODEL;

    // ---- embed ----
    embed_kernel<<<(NTOK * DMODEL) / 256, 256>>>(x, pe_input, emb_w, emb_b, h);

    // ---- encoder ----
    for (int l = 0; l < 4; l++) {
        const float* ln = enc_ln + (size_t)l * 2 * 2 * DMODEL;
        attention_block(h, h, enc_attn_w + (size_t)l * WS4, enc_attn_b + (size_t)l * 4 * DMODEL, S);
        ln_kernel<<<NTOK, 128>>>(h, tmp, ln, h);
        gemm(1, h,  enc_ff_w1 + (size_t)l * W1S, enc_ff_b1 + (size_t)l * DFF,    ff,  NTOK, DFF,    DMODEL);
        gemm(0, ff, enc_ff_w2 + (size_t)l * W2S, enc_ff_b2 + (size_t)l * DMODEL, tmp, NTOK, DMODEL, DFF);
        ln_kernel<<<NTOK, 128>>>(h, tmp, ln + 2 * DMODEL, h);
    }
    ln_kernel<<<NTOK, 128>>>(h, nullptr, enc_final_ln, z);

    // ---- decoder ----
    dec_init_kernel<<<(NTOK * DMODEL) / 256, 256>>>(out_pos_emb, o);
    for (int l = 0; l < 4; l++) {
        const float* ln = dec_ln + (size_t)l * 3 * 2 * DMODEL;
        attention_block(o, o, dec_self_w + (size_t)l * WS4, dec_self_b + (size_t)l * 4 * DMODEL, S);
        ln_kernel<<<NTOK, 128>>>(o, tmp, ln, o);
        attention_block(o, z, dec_cross_w + (size_t)l * WS4, dec_cross_b + (size_t)l * 4 * DMODEL, S);
        ln_kernel<<<NTOK, 128>>>(o, tmp, ln + 2 * DMODEL, o);
        gemm(1, o,  dec_ff_w1 + (size_t)l * W1S, dec_ff_b1 + (size_t)l * DFF,    ff,  NTOK, DFF,    DMODEL);
        gemm(0, ff, dec_ff_w2 + (size_t)l * W2S, dec_ff_b2 + (size_t)l * DMODEL, tmp, NTOK, DMODEL, DFF);
        ln_kernel<<<NTOK, 128>>>(o, tmp, ln + 4 * DMODEL, o);
    }
    ln_kernel<<<NTOK, 128>>>(o, nullptr, dec_final_ln, tmp);

    // ---- prediction head ----
    pred_kernel<<<(NTOK * 32) / 256, 256>>>(tmp, pred_w, pred_b, (float*)d_out);
}

// round 3
// speedup vs baseline: 2.3482x; 2.3482x over previous
#include <cuda_runtime.h>
#include <cuda_bf16.h>
#include <cstdint>
#include <cstddef>

// ---------------------------------------------------------------------------
// TRecTransformer: linear-attention encoder/decoder.
// GEMMs: bf16 mma.sync (m16n8k16) with 3-term hi/lo split (near-fp32 accuracy).
// ---------------------------------------------------------------------------

#define NTOK   16384
#define DMODEL 512
#define DFF    2048
#define LSEQ   4096
#define SCH    16

// ---- scratch layout (floats) ----
#define SZ      ((size_t)NTOK * DMODEL)
#define OFF_H    (0*SZ)
#define OFF_Z    (1*SZ)
#define OFF_O    (2*SZ)
#define OFF_Q    (3*SZ)
#define OFF_K    (4*SZ)
#define OFF_V    (5*SZ)
#define OFF_ATTN (6*SZ)
#define OFF_TMP  (7*SZ)
#define OFF_FF   (8*SZ)
#define OFF_PKV  (12*SZ)
#define OFF_PKS  (OFF_PKV + (size_t)SCH*32*4096)
#define OFF_KV   (OFF_PKS + (size_t)SCH*32*64)
#define OFF_KS   (OFF_KV  + (size_t)32*4096)
#define OFF_WT   (OFF_KS + 2048)
#define WT_ENC_ATTN  (OFF_WT)
#define WT_DEC_SELF  (OFF_WT + (size_t)16*262144)
#define WT_DEC_CROSS (OFF_WT + (size_t)32*262144)
#define WT_FF1       (OFF_WT + (size_t)48*262144)
#define WT_FF2       (WT_FF1 + (size_t)8*1048576)
#define TOTAL_F      (WT_FF2 + (size_t)8*1048576)

__device__ float g_scratch[TOTAL_F];

// ---------------------------------------------------------------------------
// helpers
// ---------------------------------------------------------------------------
__device__ __forceinline__ uint32_t smem_u32(const void* p) {
    uint32_t a;
    asm("{ .reg .u64 t; cvta.to.shared.u64 t, %1; cvt.u32.u64 %0, t; }" : "=r"(a) : "l"(p));
    return a;
}
__device__ __forceinline__ void ldsm4(uint32_t* r, uint32_t addr) {
    asm volatile("ldmatrix.sync.aligned.m8n8.x4.shared.b16 {%0,%1,%2,%3}, [%4];"
        : "=r"(r[0]), "=r"(r[1]), "=r"(r[2]), "=r"(r[3]) : "r"(addr));
}
__device__ __forceinline__ void mma_bf16(float* c, const uint32_t* a, const uint32_t* b) {
    asm volatile(
        "mma.sync.aligned.m16n8k16.row.col.f32.bf16.bf16.f32 "
        "{%0,%1,%2,%3}, {%4,%5,%6,%7}, {%8,%9}, {%0,%1,%2,%3};"
        : "+f"(c[0]), "+f"(c[1]), "+f"(c[2]), "+f"(c[3])
        : "r"(a[0]), "r"(a[1]), "r"(a[2]), "r"(a[3]), "r"(b[0]), "r"(b[1]));
}
// split float4 into bf16 hi pair-regs and lo pair-regs
__device__ __forceinline__ void split4(float4 v, uint2& h, uint2& l) {
    __nv_bfloat162 h0 = __floats2bfloat162_rn(v.x, v.y);
    __nv_bfloat162 h1 = __floats2bfloat162_rn(v.z, v.w);
    float2 f0 = __bfloat1622float2(h0);
    float2 f1 = __bfloat1622float2(h1);
    __nv_bfloat162 l0 = __floats2bfloat162_rn(v.x - f0.x, v.y - f0.y);
    __nv_bfloat162 l1 = __floats2bfloat162_rn(v.z - f1.x, v.w - f1.y);
    h.x = *reinterpret_cast<uint32_t*>(&h0); h.y = *reinterpret_cast<uint32_t*>(&h1);
    l.x = *reinterpret_cast<uint32_t*>(&l0); l.y = *reinterpret_cast<uint32_t*>(&l1);
}

// ---------------------------------------------------------------------------
// GEMM: C[M,N] = act(A[M,K] @ Wt[N,K]^T + bias). bf16 3x-split mma.sync.
// 128x128 tile, Kc=32, 256 threads, double-buffered smem.
// smem per matrix: 128 rows x 40 bf16 (pad 8) = 10240 B. 4 mats x 2 stages.
// ACT: 0 none, 1 relu, 2 phi = elu+1.
// ---------------------------------------------------------------------------
#define SMEM_DYN (81920)
#define ROWB 80            // bytes per smem row
#define MATB 10240         // bytes per matrix
#define STGB 40960         // bytes per stage

template<int ACT>
__global__ __launch_bounds__(256) void gemm_tc(
    const float* __restrict__ A, const float* __restrict__ Wt,
    const float* __restrict__ bias, float* __restrict__ C,
    int M, int N, int K)
{
    extern __shared__ __nv_bfloat16 sm[];
    const uint32_t smB = smem_u32(sm);

    const int tid = threadIdx.x, lane = tid & 31, wid = tid >> 5;
    const int row0 = blockIdx.y * 128, col0 = blockIdx.x * 128;
    const int wm = wid & 1, wn = wid >> 1;     // 2 x 4 warp grid

    float acc[4][4][4];
    #pragma unroll
    for (int i = 0; i < 4; i++)
        #pragma unroll
        for (int j = 0; j < 4; j++)
            #pragma unroll
            for (int e = 0; e < 4; e++) acc[i][j][e] = 0.f;

    // producer mapping: 4 passes of 32 rows, 8 float4 per row
    const int pr = tid >> 3;           // row within 32-row group
    const int pc = (tid & 7) * 4;      // float col within 32-chunk
    const float* Abase = A  + (size_t)(row0 + pr) * K + pc;
    const float* Wbase = Wt + (size_t)(col0 + pr) * K + pc;

    // ldmatrix per-lane byte offsets
    const uint32_t aoff = (uint32_t)((wm * 64 + (lane & 7) + ((lane >> 3) & 1) * 8) * ROWB
                                     + (lane >> 4) * 16);
    const uint32_t boff = (uint32_t)((wn * 32 + (lane >> 4) * 8 + (lane & 7)) * ROWB
                                     + ((lane >> 3) & 1) * 16);

    const int NC = K / 32;
    float4 pa[4], pw[4];

    auto ldG = [&](int chunk) {
        const int k0 = chunk * 32;
        #pragma unroll
        for (int p = 0; p < 4; p++) {
            pa[p] = *(const float4*)(Abase + (size_t)p * 32 * K + k0);
            pw[p] = *(const float4*)(Wbase + (size_t)p * 32 * K + k0);
        }
    };
    auto stS = [&](int stage) {
        __nv_bfloat16* s0 = sm + stage * (STGB / 2);
        #pragma unroll
        for (int p = 0; p < 4; p++) {
            const int r = p * 32 + pr;
            uint2 h, l;
            split4(pa[p], h, l);
            *(uint2*)(s0 + r * 40 + pc)        = h;   // Ah
            *(uint2*)(s0 + 5120 + r * 40 + pc) = l;   // Al
            split4(pw[p], h, l);
            *(uint2*)(s0 + 10240 + r * 40 + pc) = h;  // Bh
            *(uint2*)(s0 + 15360 + r * 40 + pc) = l;  // Bl
        }
    };
    auto compute = [&](int stage) {
        const uint32_t base = smB + stage * STGB;
        #pragma unroll
        for (int ks = 0; ks < 2; ks++) {
            uint32_t ah[4][4], al[4][4], bh[4][2], bl[4][2];
            #pragma unroll
            for (int mi = 0; mi < 4; mi++) {
                ldsm4(ah[mi], base + aoff + mi * 1280 + ks * 32);
                ldsm4(al[mi], base + MATB + aoff + mi * 1280 + ks * 32);
            }
            #pragma unroll
            for (int j = 0; j < 2; j++) {
                uint32_t t[4];
                ldsm4(t, base + 2 * MATB + boff + j * 1280 + ks * 32);
                bh[2 * j][0] = t[0]; bh[2 * j][1] = t[1];
                bh[2 * j + 1][0] = t[2]; bh[2 * j + 1][1] = t[3];
                ldsm4(t, base + 3 * MATB + boff + j * 1280 + ks * 32);
                bl[2 * j][0] = t[0]; bl[2 * j][1] = t[1];
                bl[2 * j + 1][0] = t[2]; bl[2 * j + 1][1] = t[3];
            }
            #pragma unroll
            for (int mi = 0; mi < 4; mi++)
                #pragma unroll
                for (int ni = 0; ni < 4; ni++) {
                    mma_bf16(acc[mi][ni], ah[mi], bh[ni]);
                    mma_bf16(acc[mi][ni], ah[mi], bl[ni]);
                    mma_bf16(acc[mi][ni], al[mi], bh[ni]);
                }
        }
    };

    ldG(0);
    stS(0);
    __syncthreads();
    for (int c = 0; c < NC; c++) {
        if (c + 1 < NC) ldG(c + 1);
        compute(c & 1);
        if (c + 1 < NC) stS((c + 1) & 1);
        __syncthreads();
    }

    // epilogue
    const int gm0 = row0 + wm * 64;
    const int gn0 = col0 + wn * 32;
    #pragma unroll
    for (int ni = 0; ni < 4; ni++) {
        const int cn = gn0 + ni * 8 + (lane & 3) * 2;
        const float b0 = bias[cn], b1 = bias[cn + 1];
        #pragma unroll
        for (int mi = 0; mi < 4; mi++) {
            const int rm = gm0 + mi * 16 + (lane >> 2);
            float t0 = acc[mi][ni][0] + b0;
            float t1 = acc[mi][ni][1] + b1;
            float t2 = acc[mi][ni][2] + b0;
            float t3 = acc[mi][ni][3] + b1;
            if (ACT == 1) {
                t0 = fmaxf(t0, 0.f); t1 = fmaxf(t1, 0.f);
                t2 = fmaxf(t2, 0.f); t3 = fmaxf(t3, 0.f);
            }
            if (ACT == 2) {
                t0 = t0 > 0.f ? t0 + 1.f : __expf(t0);
                t1 = t1 > 0.f ? t1 + 1.f : __expf(t1);
                t2 = t2 > 0.f ? t2 + 1.f : __expf(t2);
                t3 = t3 > 0.f ? t3 + 1.f : __expf(t3);
            }
            float2 v0; v0.x = t0; v0.y = t1;
            float2 v1; v1.x = t2; v1.y = t3;
            *(float2*)&C[(size_t)rm * N + cn]       = v0;
            *(float2*)&C[(size_t)(rm + 8) * N + cn] = v1;
        }
    }
}

// ---------------------------------------------------------------------------
// batched weight transpose: Wt[z][n,k] = W[z][k,n]
// ---------------------------------------------------------------------------
__global__ __launch_bounds__(256) void transpose_w(
    const float* __restrict__ W, float* __restrict__ Wt, int K, int N)
{
    __shared__ float t[32][33];
    const size_t mo = (size_t)blockIdx.z * K * N;
    const float* Wm = W + mo;
    float* Wtm = Wt + mo;
    const int n0 = blockIdx.x * 32, k0 = blockIdx.y * 32;
    const int tx = threadIdx.x & 31, ty = threadIdx.x >> 5;
    #pragma unroll
    for (int i = 0; i < 32; i += 8)
        t[ty + i][tx] = Wm[(size_t)(k0 + ty + i) * N + n0 + tx];
    __syncthreads();
    #pragma unroll
    for (int i = 0; i < 32; i += 8)
        Wtm[(size_t)(n0 + ty + i) * K + k0 + tx] = t[tx][ty + i];
}

// ---------------------------------------------------------------------------
// linear-attention kernels (unchanged from passing baseline)
// ---------------------------------------------------------------------------
__global__ __launch_bounds__(256) void kv_partial(
    const float* __restrict__ Kt, const float* __restrict__ Vt,
    float* __restrict__ pkv, float* __restrict__ pks)
{
    const int bh = blockIdx.x, ch = blockIdx.y;
    const int b = bh >> 3, h = bh & 7;
    const int tid = threadIdx.x;
    __shared__ float Ks[4][64], Vs[4][64];

    float acc[16];
    #pragma unroll
    for (int j = 0; j < 16; j++) acc[j] = 0.f;
    float ksa = 0.f;

    const int s0 = ch * (LSEQ / SCH);
    const size_t base = ((size_t)b * LSEQ) * DMODEL + h * 64;
    const int r = tid >> 6, d = tid & 63;

    for (int s = s0; s < s0 + LSEQ / SCH; s += 4) {
        const size_t off = base + (size_t)(s + r) * DMODEL + d;
        Ks[r][d] = Kt[off];
        Vs[r][d] = Vt[off];
        __syncthreads();
        #pragma unroll
        for (int rr = 0; rr < 4; rr++) {
            #pragma unroll
            for (int j = 0; j < 16; j++) {
                const int flat = j * 256 + tid;
                acc[j] = fmaf(Ks[rr][flat >> 6], Vs[rr][flat & 63], acc[j]);
            }
            if (tid < 64) ksa += Ks[rr][tid];
        }
        __syncthreads();
    }
    float* o = pkv + ((size_t)ch * 32 + bh) * 4096;
    #pragma unroll
    for (int j = 0; j < 16; j++) o[j * 256 + tid] = acc[j];
    if (tid < 64) pks[((size_t)ch * 32 + bh) * 64 + tid] = ksa;
}

__global__ __launch_bounds__(256) void kv_reduce(
    const float* __restrict__ pkv, const float* __restrict__ pks,
    float* __restrict__ kv, float* __restrict__ ks)
{
    const int bh = blockIdx.x, tid = threadIdx.x;
    for (int e = tid; e < 4096; e += 256) {
        float s = 0.f;
        #pragma unroll
        for (int c = 0; c < SCH; c++) s += pkv[((size_t)c * 32 + bh) * 4096 + e];
        kv[(size_t)bh * 4096 + e] = s;
    }
    if (tid < 64) {
        float s = 0.f;
        #pragma unroll
        for (int c = 0; c < SCH; c++) s += pks[((size_t)c * 32 + bh) * 64 + tid];
        ks[bh * 64 + tid] = s;
    }
}

__global__ __launch_bounds__(256) void attn_out(
    const float* __restrict__ Q, const float* __restrict__ kv,
    const float* __restrict__ ksum, float* __restrict__ O)
{
    const int bh = blockIdx.x, b = bh >> 3, h = bh & 7;
    __shared__ float kvs[64][64];
    __shared__ float kss[64];
    const int tid = threadIdx.x;
    for (int e = tid; e < 4096; e += 256) kvs[e >> 6][e & 63] = kv[(size_t)bh * 4096 + e];
    if (tid < 64) kss[tid] = ksum[bh * 64 + tid];
    __syncthreads();

    const int warp = tid >> 5, lane = tid & 31;
    const int tpb = LSEQ / gridDim.y;
    const int l0 = blockIdx.y * tpb;

    for (int l = l0 + warp; l < l0 + tpb; l += 8) {
        const float* q = Q + ((size_t)(b * LSEQ + l)) * DMODEL + h * 64;
        const float q0 = q[lane], q1 = q[lane + 32];
        float zd = q0 * kss[lane] + q1 * kss[lane + 32];
        #pragma unroll
        for (int o = 16; o > 0; o >>= 1) zd += __shfl_xor_sync(0xffffffffu, zd, o);
        const float z = 1.f / (zd + 1e-6f);

        float a0 = 0.f, a1 = 0.f;
        #pragma unroll
        for (int dd = 0; dd < 32; dd++) {
            const float qd = __shfl_sync(0xffffffffu, q0, dd);
            a0 = fmaf(qd, kvs[dd][lane],      a0);
            a1 = fmaf(qd, kvs[dd][lane + 32], a1);
        }
        #pragma unroll
        for (int dd = 0; dd < 32; dd++) {
            const float qd = __shfl_sync(0xffffffffu, q1, dd);
            a0 = fmaf(qd, kvs[dd + 32][lane],      a0);
            a1 = fmaf(qd, kvs[dd + 32][lane + 32], a1);
        }
        float* op = O + ((size_t)(b * LSEQ + l)) * DMODEL + h * 64;
        op[lane]      = a0 * z;
        op[lane + 32] = a1 * z;
    }
}

__global__ __launch_bounds__(128) void ln_kernel(
    const float* __restrict__ X, const float* __restrict__ R,
    const float* __restrict__ gb, float* __restrict__ Y)
{
    const int t = blockIdx.x, tid = threadIdx.x;
    const float* x = X + (size_t)t * DMODEL;
    float v[4];
    float s = 0.f;
    #pragma unroll
    for (int i = 0; i < 4; i++) {
        float val = x[tid + i * 128];
        if (R) val += R[(size_t)t * DMODEL + tid + i * 128];
        v[i] = val; s += val;
    }
    __shared__ float red[4];
    #pragma unroll
    for (int o = 16; o > 0; o >>= 1) s += __shfl_xor_sync(0xffffffffu, s, o);
    if ((tid & 31) == 0) red[tid >> 5] = s;
    __syncthreads();
    const float mu = (red[0] + red[1] + red[2] + red[3]) * (1.f / DMODEL);
    float qq = 0.f;
    #pragma unroll
    for (int i = 0; i < 4; i++) { const float dd = v[i] - mu; qq += dd * dd; }
    #pragma unroll
    for (int o = 16; o > 0; o >>= 1) qq += __shfl_xor_sync(0xffffffffu, qq, o);
    __syncthreads();
    if ((tid & 31) == 0) red[tid >> 5] = qq;
    __syncthreads();
    const float var = (red[0] + red[1] + red[2] + red[3]) * (1.f / DMODEL);
    const float rstd = rsqrtf(var + 1e-5f);
    #pragma unroll
    for (int i = 0; i < 4; i++) {
        const int j = tid + i * 128;
        Y[(size_t)t * DMODEL + j] = (v[i] - mu) * rstd * gb[j] + gb[DMODEL + j];
    }
}

__global__ void embed_kernel(
    const float* __restrict__ x, const float* __restrict__ pe,
    const float* __restrict__ ew, const float* __restrict__ eb,
    float* __restrict__ h)
{
    const size_t idx = (size_t)blockIdx.x * blockDim.x + threadIdx.x;
    const int tok = (int)(idx >> 9);
    const int j   = (int)(idx & 511);
    const int l   = tok & (LSEQ - 1);
    float val;
    if (j < 256) val = x[(size_t)tok * 2] * ew[j] + x[(size_t)tok * 2 + 1] * ew[256 + j] + eb[j];
    else         val = pe[(size_t)l * 256 + (j - 256)];
    h[idx] = val;
}

__global__ void dec_init_kernel(const float* __restrict__ ope, float* __restrict__ o)
{
    const size_t idx = (size_t)blockIdx.x * blockDim.x + threadIdx.x;
    const size_t tok = idx >> 9;
    o[idx] = ope[((tok & (LSEQ - 1)) << 9) | (idx & 511)];
}

__global__ void pred_kernel(
    const float* __restrict__ Xf, const float* __restrict__ pw,
    const float* __restrict__ pb, float* __restrict__ out)
{
    const int gw = (int)(((size_t)blockIdx.x * blockDim.x + threadIdx.x) >> 5);
    const int lane = threadIdx.x & 31;
    if (gw >= NTOK) return;
    const float* xr = Xf + (size_t)gw * DMODEL;
    float a0 = 0.f, a1 = 0.f;
    #pragma unroll 4
    for (int j = lane; j < DMODEL; j += 32) {
        const float v = xr[j];
        a0 = fmaf(v, pw[2 * j],     a0);
        a1 = fmaf(v, pw[2 * j + 1], a1);
    }
    #pragma unroll
    for (int o = 16; o > 0; o >>= 1) {
        a0 += __shfl_xor_sync(0xffffffffu, a0, o);
        a1 += __shfl_xor_sync(0xffffffffu, a1, o);
    }
    if (lane == 0) { out[2 * gw] = a0 + pb[0]; out[2 * gw + 1] = a1 + pb[1]; }
}

// ---------------------------------------------------------------------------
// Host orchestration
// ---------------------------------------------------------------------------
static inline void gemm(int act, const float* A, const float* Wt, const float* b,
                        float* C, int M, int N, int K)
{
    dim3 grid(N / 128, M / 128);
    if (act == 0)      gemm_tc<0><<<grid, 256, SMEM_DYN>>>(A, Wt, b, C, M, N, K);
    else if (act == 1) gemm_tc<1><<<grid, 256, SMEM_DYN>>>(A, Wt, b, C, M, N, K);
    else               gemm_tc<2><<<grid, 256, SMEM_DYN>>>(A, Wt, b, C, M, N, K);
}

static void attention_block(const float* xq, const float* xkv,
                            const float* wt, const float* b, float* S)
{
    float* q    = S + OFF_Q;
    float* k    = S + OFF_K;
    float* v    = S + OFF_V;
    float* attn = S + OFF_ATTN;
    float* tmp  = S + OFF_TMP;
    const size_t WS = (size_t)DMODEL * DMODEL;

    gemm(2, xq,  wt + 0 * WS, b + 0 * DMODEL, q, NTOK, DMODEL, DMODEL);
    gemm(2, xkv, wt + 1 * WS, b + 1 * DMODEL, k, NTOK, DMODEL, DMODEL);
    gemm(0, xkv, wt + 2 * WS, b + 2 * DMODEL, v, NTOK, DMODEL, DMODEL);

    kv_partial<<<dim3(32, SCH), 256>>>(k, v, S + OFF_PKV, S + OFF_PKS);
    kv_reduce<<<32, 256>>>(S + OFF_PKV, S + OFF_PKS, S + OFF_KV, S + OFF_KS);
    attn_out<<<dim3(32, 32), 256>>>(q, S + OFF_KV, S + OFF_KS, attn);

    gemm(0, attn, wt + 3 * WS, b + 3 * DMODEL, tmp, NTOK, DMODEL, DMODEL);
}

extern "C" void kernel_launch(void* const* d_in, const int* in_sizes, int n_in,
                              void* d_out, int out_size)
{
    const float* x            = (const float*)d_in[0];
    const float* out_pos_emb  = (const float*)d_in[1];
    const float* pe_input     = (const float*)d_in[2];
    const float* emb_w        = (const float*)d_in[3];
    const float* emb_b        = (const float*)d_in[4];
    const float* enc_attn_w   = (const float*)d_in[5];
    const float* enc_attn_b   = (const float*)d_in[6];
    const float* enc_ln       = (const float*)d_in[7];
    const float* enc_ff_w1    = (const float*)d_in[8];
    const float* enc_ff_b1    = (const float*)d_in[9];
    const float* enc_ff_w2    = (const float*)d_in[10];
    const float* enc_ff_b2    = (const float*)d_in[11];
    const float* enc_final_ln = (const float*)d_in[12];
    const float* dec_self_w   = (const float*)d_in[13];
    const float* dec_self_b   = (const float*)d_in[14];
    const float* dec_cross_w  = (const float*)d_in[15];
    const float* dec_cross_b  = (const float*)d_in[16];
    const float* dec_ln       = (const float*)d_in[17];
    const float* dec_ff_w1    = (const float*)d_in[18];
    const float* dec_ff_b1    = (const float*)d_in[19];
    const float* dec_ff_w2    = (const float*)d_in[20];
    const float* dec_ff_b2    = (const float*)d_in[21];
    const float* dec_final_ln = (const float*)d_in[22];
    const float* pred_w       = (const float*)d_in[23];
    const float* pred_b       = (const float*)d_in[24];

    cudaFuncSetAttribute(gemm_tc<0>, cudaFuncAttributeMaxDynamicSharedMemorySize, SMEM_DYN);
    cudaFuncSetAttribute(gemm_tc<1>, cudaFuncAttributeMaxDynamicSharedMemorySize, SMEM_DYN);
    cudaFuncSetAttribute(gemm_tc<2>, cudaFuncAttributeMaxDynamicSharedMemorySize, SMEM_DYN);

    float* S = nullptr;
    cudaGetSymbolAddress((void**)&S, g_scratch);

    float* h   = S + OFF_H;
    float* z   = S + OFF_Z;
    float* o   = S + OFF_O;
    float* tmp = S + OFF_TMP;
    float* ff  = S + OFF_FF;

    // ---- transpose all weights into [N,K] layout ----
    transpose_w<<<dim3(16, 16, 16), 256>>>(enc_attn_w,  S + WT_ENC_ATTN,  512, 512);
    transpose_w<<<dim3(16, 16, 16), 256>>>(dec_self_w,  S + WT_DEC_SELF,  512, 512);
    transpose_w<<<dim3(16, 16, 16), 256>>>(dec_cross_w, S + WT_DEC_CROSS, 512, 512);
    transpose_w<<<dim3(64, 16, 4),  256>>>(enc_ff_w1, S + WT_FF1,                     512, 2048);
    transpose_w<<<dim3(64, 16, 4),  256>>>(dec_ff_w1, S + WT_FF1 + (size_t)4*1048576, 512, 2048);
    transpose_w<<<dim3(16, 64, 4),  256>>>(enc_ff_w2, S + WT_FF2,                     2048, 512);
    transpose_w<<<dim3(16, 64, 4),  256>>>(dec_ff_w2, S + WT_FF2 + (size_t)4*1048576, 2048, 512);

    const size_t WT4 = (size_t)4 * DMODEL * DMODEL;
    const size_t W1S = (size_t)DFF * DMODEL;
    const size_t W2S = (size_t)DMODEL * DFF;

    // ---- embed ----
    embed_kernel<<<(NTOK * DMODEL) / 256, 256>>>(x, pe_input, emb_w, emb_b, h);

    // ---- encoder ----
    for (int l = 0; l < 4; l++) {
        const float* ln = enc_ln + (size_t)l * 2 * 2 * DMODEL;
        attention_block(h, h, S + WT_ENC_ATTN + (size_t)l * WT4,
                        enc_attn_b + (size_t)l * 4 * DMODEL, S);
        ln_kernel<<<NTOK, 128>>>(h, tmp, ln, h);
        gemm(1, h,  S + WT_FF1 + (size_t)l * W1S, enc_ff_b1 + (size_t)l * DFF,    ff,  NTOK, DFF,    DMODEL);
        gemm(0, ff, S + WT_FF2 + (size_t)l * W2S, enc_ff_b2 + (size_t)l * DMODEL, tmp, NTOK, DMODEL, DFF);
        ln_kernel<<<NTOK, 128>>>(h, tmp, ln + 2 * DMODEL, h);
    }
    ln_kernel<<<NTOK, 128>>>(h, nullptr, enc_final_ln, z);

    // ---- decoder ----
    dec_init_kernel<<<(NTOK * DMODEL) / 256, 256>>>(out_pos_emb, o);
    for (int l = 0; l < 4; l++) {
        const float* ln = dec_ln + (size_t)l * 3 * 2 * DMODEL;
        attention_block(o, o, S + WT_DEC_SELF + (size_t)l * WT4,
                        dec_self_b + (size_t)l * 4 * DMODEL, S);
        ln_kernel<<<NTOK, 128>>>(o, tmp, ln, o);
        attention_block(o, z, S + WT_DEC_CROSS + (size_t)l * WT4,
                        dec_cross_b + (size_t)l * 4 * DMODEL, S);
        ln_kernel<<<NTOK, 128>>>(o, tmp, ln + 2 * DMODEL, o);
        gemm(1, o,  S + WT_FF1 + (size_t)(4 + l) * W1S, dec_ff_b1 + (size_t)l * DFF,    ff,  NTOK, DFF,    DMODEL);
        gemm(0, ff, S + WT_FF2 + (size_t)(4 + l) * W2S, dec_ff_b2 + (size_t)l * DMODEL, tmp, NTOK, DMODEL, DFF);
        ln_kernel<<<NTOK, 128>>>(o, tmp, ln + 4 * DMODEL, o);
    }
    ln_kernel<<<NTOK, 128>>>(o, nullptr, dec_final_ln, tmp);

    // ---- prediction head ----
    pred_kernel<<<(NTOK * 32) / 256, 256>>>(tmp, pred_w, pred_b, (float*)d_out);
}